// round 1
// baseline (speedup 1.0000x reference)
#include <cuda_runtime.h>
#include <math.h>

#define NN 32768
#define DD 256
#define KK 4096
#define OUT_SCALAR_BASE (NN * DD)       // 8388608
#define OUT_IDX_BASE    (NN * DD + 3)   // 8388611

// ---------------- scratch (no allocations allowed) ----------------
__device__ float  g_xx[NN];
__device__ float  g_ee[KK];
__device__ int    g_idx[NN];
__device__ int    g_cnt[KK];
__device__ double g_sq;

// ---------------- init scratch (graph replays re-run this) ----------------
__global__ void k_init() {
    int i = blockIdx.x * blockDim.x + threadIdx.x;
    if (i < KK) g_cnt[i] = 0;
    if (i == 0) g_sq = 0.0;
}

// ---------------- row squared-norms: warp per row, XLA-GPU-style tree ------
// lane accumulates 8 strided terms sequentially, then butterfly tree.
__global__ void k_rownorm(const float* __restrict__ v, int rows, int which) {
    int gw   = (blockIdx.x * blockDim.x + threadIdx.x) >> 5;
    int lane = threadIdx.x & 31;
    if (gw >= rows) return;
    const float* p = v + (size_t)gw * DD;
    float s = 0.f;
#pragma unroll
    for (int j = 0; j < 8; j++) {
        float t = p[lane + 32 * j];
        s = __fadd_rn(s, __fmul_rn(t, t));
    }
#pragma unroll
    for (int off = 16; off; off >>= 1)
        s = __fadd_rn(s, __shfl_xor_sync(0xffffffffu, s, off));
    if (lane == 0) {
        if (which == 0) g_xx[gw] = s;
        else            g_ee[gw] = s;
    }
}

// ---------------- fused fp32 GEMM + argmin -------------------------------
// CTA: 128 rows x (loop over 32 tiles of 128 codes). 256 threads, 8x8 per
// thread, k-chunk 8. Distance replicates reference rounding exactly:
//   d = fl( fl(xx + ee) - fl(2*dot) ), argmin with FIRST-index tie-break.
__global__ __launch_bounds__(256, 2) void k_gemm_argmin(
        const float* __restrict__ x, const float* __restrict__ emb) {
    __shared__ float xs[8][132];
    __shared__ float es[8][132];
    __shared__ float xxs[128];
    __shared__ float ees[128];
    __shared__ unsigned long long red[128 * 16];

    const int tid  = threadIdx.x;
    const int row0 = blockIdx.x * 128;
    const int tr   = tid >> 4;      // 0..15 -> row group of 8
    const int tc   = tid & 15;      // 0..15 -> code group of 8
    const int lr   = tid >> 1;      // 0..127 load row/code
    const int lq   = (tid & 1) * 4; // 0 or 4 within 8-wide k-chunk

    if (tid < 128) xxs[tid] = g_xx[row0 + tid];

    float bval[8];
    int   bidx[8];
#pragma unroll
    for (int i = 0; i < 8; i++) { bval[i] = 3.4e38f; bidx[i] = 0; }

    for (int tile = 0; tile < 32; tile++) {
        const int k0 = tile * 128;
        __syncthreads();                    // protect ees from prior epilogue readers
        if (tid < 128) ees[tid] = g_ee[k0 + tid];

        float acc[8][8];
#pragma unroll
        for (int i = 0; i < 8; i++)
#pragma unroll
            for (int j = 0; j < 8; j++) acc[i][j] = 0.f;

        for (int dc = 0; dc < 32; dc++) {
            const int d0 = dc * 8;
            float4 xv = *(const float4*)(x   + (size_t)(row0 + lr) * DD + d0 + lq);
            float4 ev = *(const float4*)(emb + (size_t)(k0   + lr) * DD + d0 + lq);
            __syncthreads();
            xs[lq + 0][lr] = xv.x; xs[lq + 1][lr] = xv.y;
            xs[lq + 2][lr] = xv.z; xs[lq + 3][lr] = xv.w;
            es[lq + 0][lr] = ev.x; es[lq + 1][lr] = ev.y;
            es[lq + 2][lr] = ev.z; es[lq + 3][lr] = ev.w;
            __syncthreads();
#pragma unroll
            for (int kk = 0; kk < 8; kk++) {
                float4 a0 = *(const float4*)&xs[kk][tr * 8];
                float4 a1 = *(const float4*)&xs[kk][tr * 8 + 4];
                float4 b0 = *(const float4*)&es[kk][tc * 8];
                float4 b1 = *(const float4*)&es[kk][tc * 8 + 4];
                float a[8] = {a0.x, a0.y, a0.z, a0.w, a1.x, a1.y, a1.z, a1.w};
                float b[8] = {b0.x, b0.y, b0.z, b0.w, b1.x, b1.y, b1.z, b1.w};
#pragma unroll
                for (int i = 0; i < 8; i++)
#pragma unroll
                    for (int j = 0; j < 8; j++)
                        acc[i][j] = __fmaf_rn(a[i], b[j], acc[i][j]);
            }
        }
        // epilogue: exact reference rounding, running first-index argmin
#pragma unroll
        for (int i = 0; i < 8; i++) {
            const float xr = xxs[tr * 8 + i];
#pragma unroll
            for (int j = 0; j < 8; j++) {
                float two = __fmul_rn(2.0f, acc[i][j]);           // exact
                float d   = __fadd_rn(__fadd_rn(xr, ees[tc * 8 + j]), -two);
                int   c   = k0 + tc * 8 + j;
                if (d < bval[i]) { bval[i] = d; bidx[i] = c; }    // strict <: keep lowest idx
            }
        }
    }

    __syncthreads();
#pragma unroll
    for (int i = 0; i < 8; i++) {
        int r = tr * 8 + i;
        // distances are ~256 > 0: positive-float bit pattern is order-preserving.
        red[r * 16 + tc] =
            (((unsigned long long)__float_as_uint(bval[i])) << 32) | (unsigned)bidx[i];
    }
    __syncthreads();
    if (tid < 128) {
        unsigned long long m = red[tid * 16];
#pragma unroll
        for (int t = 1; t < 16; t++) {
            unsigned long long vv = red[tid * 16 + t];
            if (vv < m) m = vv;                                   // min val, then min idx
        }
        g_idx[row0 + tid] = (int)(m & 0xffffffffull);
    }
}

// ---------------- gather + straight-through output + MSE sum --------------
__global__ void k_gather(const float* __restrict__ x, const float* __restrict__ emb,
                         const float* __restrict__ mask, float* __restrict__ out) {
    __shared__ double sh[8];
    double local = 0.0;
    for (int id = blockIdx.x * blockDim.x + threadIdx.x; id < NN * DD;
         id += gridDim.x * blockDim.x) {
        int row = id >> 8;
        int col = id & 255;
        float q  = __fmul_rn(emb[(size_t)g_idx[row] * DD + col], mask[row]);
        float xv = x[id];
        float d1 = __fadd_rn(q, -xv);            // fl(quantized - x)
        out[id]  = __fadd_rn(xv, d1);            // fl(x + fl(q - x))  (NOT just q!)
        float sq = __fmul_rn(d1, d1);
        local += (double)sq;
    }
#pragma unroll
    for (int off = 16; off; off >>= 1)
        local += __shfl_xor_sync(0xffffffffu, local, off);
    int lane = threadIdx.x & 31, w = threadIdx.x >> 5;
    if (lane == 0) sh[w] = local;
    __syncthreads();
    if (threadIdx.x == 0) {
        double s = 0.0;
        int nw = blockDim.x >> 5;
        for (int i = 0; i < nw; i++) s += sh[i];
        atomicAdd(&g_sq, s);
    }
}

// ---------------- histogram + index output --------------------------------
__global__ void k_hist(float* __restrict__ out) {
    int i = blockIdx.x * blockDim.x + threadIdx.x;
    if (i < NN) {
        int c = g_idx[i];
        atomicAdd(&g_cnt[c], 1);
        out[OUT_IDX_BASE + i] = (float)c;
    }
}

// ---------------- scalars: losses + perplexity ----------------------------
__global__ void k_final(float* __restrict__ out) {
    __shared__ double sh[8];
    double local = 0.0;
    for (int k = threadIdx.x; k < KK; k += blockDim.x) {
        float p = __fmul_rn((float)g_cnt[k], 1.0f / 32768.0f);  // /2^15: exact
        float t = __fmul_rn(p, logf(__fadd_rn(p, 1e-8f)));
        local += (double)t;
    }
#pragma unroll
    for (int off = 16; off; off >>= 1)
        local += __shfl_xor_sync(0xffffffffu, local, off);
    int lane = threadIdx.x & 31, w = threadIdx.x >> 5;
    if (lane == 0) sh[w] = local;
    __syncthreads();
    if (threadIdx.x == 0) {
        double H = 0.0;
        int nw = blockDim.x >> 5;
        for (int i = 0; i < nw; i++) H += sh[i];
        float perp = expf(-(float)H);
        double mse = g_sq / (double)(NN * DD);
        float ql   = (float)mse;                // q_latent_loss == e_latent_loss numerically
        out[OUT_SCALAR_BASE + 0] = __fmul_rn(0.25f, ql);  // commitment
        out[OUT_SCALAR_BASE + 1] = ql;                    // q_latent
        out[OUT_SCALAR_BASE + 2] = perp;                  // perplexity
    }
}

// ---------------- launch ---------------------------------------------------
extern "C" void kernel_launch(void* const* d_in, const int* in_sizes, int n_in,
                              void* d_out, int out_size) {
    const float* x    = (const float*)d_in[0];  // [32768, 256]
    const float* emb  = (const float*)d_in[1];  // [4096, 256]
    const float* mask = (const float*)d_in[2];  // [32768]
    float* out = (float*)d_out;

    k_init<<<(KK + 255) / 256, 256>>>();
    k_rownorm<<<(NN * 32) / 256, 256>>>(x, NN, 0);
    k_rownorm<<<(KK * 32) / 256, 256>>>(emb, KK, 1);
    k_gemm_argmin<<<NN / 128, 256>>>(x, emb);
    k_gather<<<1024, 256>>>(x, emb, mask, out);
    k_hist<<<(NN + 255) / 256, 256>>>(out);
    k_final<<<1, 256>>>(out);
}

// round 3
// speedup vs baseline: 1.0698x; 1.0698x over previous
#include <cuda_runtime.h>
#include <math.h>

#define NN 32768
#define DD 256
#define KK 4096
#define OUT_SCALAR_BASE (NN * DD)       // 8388608
#define OUT_IDX_BASE    (NN * DD + 3)   // 8388611

// ---------------- scratch (no allocations allowed) ----------------
__device__ float  g_xx[NN];
__device__ float  g_ee[KK];
__device__ int    g_idx[NN];
__device__ int    g_cnt[KK];
__device__ double g_sq;

// ---------------- init scratch (graph replays re-run this) ----------------
__global__ void k_init() {
    int i = blockIdx.x * blockDim.x + threadIdx.x;
    if (i < KK) g_cnt[i] = 0;
    if (i == 0) g_sq = 0.0;
}

// ---------------- row squared-norms: warp per row ------------------------
__global__ void k_rownorm(const float* __restrict__ v, int rows, int which) {
    int gw   = (blockIdx.x * blockDim.x + threadIdx.x) >> 5;
    int lane = threadIdx.x & 31;
    if (gw >= rows) return;
    const float* p = v + (size_t)gw * DD;
    float s = 0.f;
#pragma unroll
    for (int j = 0; j < 8; j++) {
        float t = p[lane + 32 * j];
        s = __fadd_rn(s, __fmul_rn(t, t));
    }
#pragma unroll
    for (int off = 16; off; off >>= 1)
        s = __fadd_rn(s, __shfl_xor_sync(0xffffffffu, s, off));
    if (lane == 0) {
        if (which == 0) g_xx[gw] = s;
        else            g_ee[gw] = s;
    }
}

// ---------------- fused fp32 GEMM + argmin -------------------------------
// CTA: 128 rows x 32 tiles of 128 codes. 256 threads, 8x8 thread tile.
// x staged into smem PRE-SCALED by 2 (exact), so acc == 2*dot bit-exactly and
// the epilogue is d = fl( fl(xx+ee) - acc ), identical rounding to reference.
// Code-tile mapping per thread: {tc*4+0..3} u {64+tc*4+0..3} -> conflict-free
// LDS.128 on the B operand. Double-buffered smem, 1 sync per d-chunk.
__global__ __launch_bounds__(256, 2) void k_gemm_argmin(
        const float* __restrict__ x, const float* __restrict__ emb) {
    __shared__ float xs[2][8][132];
    __shared__ float es[2][8][132];
    __shared__ float xxs[128];
    __shared__ float ees[128];
    __shared__ unsigned long long red[128 * 16];

    const int tid  = threadIdx.x;
    const int row0 = blockIdx.x * 128;
    const int tr   = tid >> 4;      // 0..15 -> row group of 8
    const int tc   = tid & 15;      // 0..15 -> code half-groups of 4
    const int lr   = tid >> 1;      // 0..127 load row/code
    const int lq   = (tid & 1) * 4; // 0 or 4 within 8-wide d-chunk

    if (tid < 128) xxs[tid] = g_xx[row0 + tid];

    const float* pX = x + (size_t)(row0 + lr) * DD + lq;

    float bval[8];
    int   bidx[8];
#pragma unroll
    for (int i = 0; i < 8; i++) { bval[i] = 3.4e38f; bidx[i] = 0; }

    for (int tile = 0; tile < 32; tile++) {
        const int k0 = tile * 128;
        const float* pE = emb + (size_t)(k0 + lr) * DD + lq;

        // prologue: prefetch d-chunk 0
        float4 xv = *(const float4*)(pX);
        float4 ev = *(const float4*)(pE);
        __syncthreads();                      // prior epilogue done reading ees
        if (tid < 128) ees[tid] = g_ee[k0 + tid];
        // stage buffer 0 (x pre-scaled by 2: exact)
        xs[0][lq + 0][lr] = 2.f * xv.x; xs[0][lq + 1][lr] = 2.f * xv.y;
        xs[0][lq + 2][lr] = 2.f * xv.z; xs[0][lq + 3][lr] = 2.f * xv.w;
        es[0][lq + 0][lr] = ev.x; es[0][lq + 1][lr] = ev.y;
        es[0][lq + 2][lr] = ev.z; es[0][lq + 3][lr] = ev.w;
        __syncthreads();

        float acc[8][8];
#pragma unroll
        for (int i = 0; i < 8; i++)
#pragma unroll
            for (int j = 0; j < 8; j++) acc[i][j] = 0.f;

        for (int dc = 0; dc < 32; dc++) {
            const int cur = dc & 1;
            float4 nxv, nev;
            if (dc < 31) {                    // prefetch next chunk (latency hidden)
                nxv = *(const float4*)(pX + (dc + 1) * 8);
                nev = *(const float4*)(pE + (dc + 1) * 8);
            }
#pragma unroll
            for (int kk = 0; kk < 8; kk++) {
                float4 a0 = *(const float4*)&xs[cur][kk][tr * 8];
                float4 a1 = *(const float4*)&xs[cur][kk][tr * 8 + 4];
                float4 b0 = *(const float4*)&es[cur][kk][tc * 4];       // codes tc*4+0..3
                float4 b1 = *(const float4*)&es[cur][kk][64 + tc * 4];  // codes 64+tc*4+0..3
                float a[8] = {a0.x, a0.y, a0.z, a0.w, a1.x, a1.y, a1.z, a1.w};
                float b[8] = {b0.x, b0.y, b0.z, b0.w, b1.x, b1.y, b1.z, b1.w};
#pragma unroll
                for (int i = 0; i < 8; i++)
#pragma unroll
                    for (int j = 0; j < 8; j++)
                        acc[i][j] = __fmaf_rn(a[i], b[j], acc[i][j]);
            }
            if (dc < 31) {
                const int nxt = cur ^ 1;      // buffer last read at dc-1: safe to overwrite
                xs[nxt][lq + 0][lr] = 2.f * nxv.x; xs[nxt][lq + 1][lr] = 2.f * nxv.y;
                xs[nxt][lq + 2][lr] = 2.f * nxv.z; xs[nxt][lq + 3][lr] = 2.f * nxv.w;
                es[nxt][lq + 0][lr] = nev.x; es[nxt][lq + 1][lr] = nev.y;
                es[nxt][lq + 2][lr] = nev.z; es[nxt][lq + 3][lr] = nev.w;
            }
            __syncthreads();
        }

        // epilogue: acc == 2*dot exactly; d = fl(fl(xx+ee) - acc). Strict < keeps
        // the lowest index; cross-thread ties resolved by packed-u64 min below.
#pragma unroll
        for (int i = 0; i < 8; i++) {
            const float xr = xxs[tr * 8 + i];
#pragma unroll
            for (int j = 0; j < 8; j++) {
                const int jj = (j < 4) ? (tc * 4 + j) : (64 + tc * 4 + (j - 4));
                float d = __fadd_rn(__fadd_rn(xr, ees[jj]), -acc[i][j]);
                int   c = k0 + jj;
                if (d < bval[i]) { bval[i] = d; bidx[i] = c; }
            }
        }
    }

    __syncthreads();
#pragma unroll
    for (int i = 0; i < 8; i++) {
        int r = tr * 8 + i;
        // distances ~256 > 0: positive-float bits are order-preserving.
        red[r * 16 + tc] =
            (((unsigned long long)__float_as_uint(bval[i])) << 32) | (unsigned)bidx[i];
    }
    __syncthreads();
    if (tid < 128) {
        unsigned long long m = red[tid * 16];
#pragma unroll
        for (int t = 1; t < 16; t++) {
            unsigned long long vv = red[tid * 16 + t];
            if (vv < m) m = vv;               // min val, then min idx
        }
        g_idx[row0 + tid] = (int)(m & 0xffffffffull);
    }
}

// ---------------- gather + straight-through output + MSE sum --------------
__global__ void k_gather(const float* __restrict__ x, const float* __restrict__ emb,
                         const float* __restrict__ mask, float* __restrict__ out) {
    __shared__ double sh[8];
    double local = 0.0;
    for (int id = blockIdx.x * blockDim.x + threadIdx.x; id < NN * DD;
         id += gridDim.x * blockDim.x) {
        int row = id >> 8;
        int col = id & 255;
        float q  = __fmul_rn(emb[(size_t)g_idx[row] * DD + col], mask[row]);
        float xv = x[id];
        float d1 = __fadd_rn(q, -xv);            // fl(quantized - x)
        out[id]  = __fadd_rn(xv, d1);            // fl(x + fl(q - x))
        float sq = __fmul_rn(d1, d1);
        local += (double)sq;
    }
#pragma unroll
    for (int off = 16; off; off >>= 1)
        local += __shfl_xor_sync(0xffffffffu, local, off);
    int lane = threadIdx.x & 31, w = threadIdx.x >> 5;
    if (lane == 0) sh[w] = local;
    __syncthreads();
    if (threadIdx.x == 0) {
        double s = 0.0;
        int nw = blockDim.x >> 5;
        for (int i = 0; i < nw; i++) s += sh[i];
        atomicAdd(&g_sq, s);
    }
}

// ---------------- histogram + index output --------------------------------
__global__ void k_hist(float* __restrict__ out) {
    int i = blockIdx.x * blockDim.x + threadIdx.x;
    if (i < NN) {
        int c = g_idx[i];
        atomicAdd(&g_cnt[c], 1);
        out[OUT_IDX_BASE + i] = (float)c;
    }
}

// ---------------- scalars: losses + perplexity ----------------------------
__global__ void k_final(float* __restrict__ out) {
    __shared__ double sh[8];
    double local = 0.0;
    for (int k = threadIdx.x; k < KK; k += blockDim.x) {
        float p = __fmul_rn((float)g_cnt[k], 1.0f / 32768.0f);  // /2^15: exact
        float t = __fmul_rn(p, logf(__fadd_rn(p, 1e-8f)));
        local += (double)t;
    }
#pragma unroll
    for (int off = 16; off; off >>= 1)
        local += __shfl_xor_sync(0xffffffffu, local, off);
    int lane = threadIdx.x & 31, w = threadIdx.x >> 5;
    if (lane == 0) sh[w] = local;
    __syncthreads();
    if (threadIdx.x == 0) {
        double H = 0.0;
        int nw = blockDim.x >> 5;
        for (int i = 0; i < nw; i++) H += sh[i];
        float perp = expf(-(float)H);
        double mse = g_sq / (double)(NN * DD);
        float ql   = (float)mse;
        out[OUT_SCALAR_BASE + 0] = __fmul_rn(0.25f, ql);  // commitment
        out[OUT_SCALAR_BASE + 1] = ql;                    // q_latent
        out[OUT_SCALAR_BASE + 2] = perp;                  // perplexity
    }
}

// ---------------- launch ---------------------------------------------------
extern "C" void kernel_launch(void* const* d_in, const int* in_sizes, int n_in,
                              void* d_out, int out_size) {
    const float* x    = (const float*)d_in[0];  // [32768, 256]
    const float* emb  = (const float*)d_in[1];  // [4096, 256]
    const float* mask = (const float*)d_in[2];  // [32768]
    float* out = (float*)d_out;

    k_init<<<(KK + 255) / 256, 256>>>();
    k_rownorm<<<(NN * 32) / 256, 256>>>(x, NN, 0);
    k_rownorm<<<(KK * 32) / 256, 256>>>(emb, KK, 1);
    k_gemm_argmin<<<NN / 128, 256>>>(x, emb);
    k_gather<<<1024, 256>>>(x, emb, mask, out);
    k_hist<<<(NN + 255) / 256, 256>>>(out);
    k_final<<<1, 256>>>(out);
}

// round 6
// speedup vs baseline: 2.2595x; 2.1122x over previous
#include <cuda_runtime.h>
#include <math.h>
#include <stdint.h>

#define NN 32768
#define DD 256
#define KK 4096
#define OUT_SCALAR_BASE (NN * DD)
#define OUT_IDX_BASE    (NN * DD + 3)
#define CAP 24
#define EPSC 0.00390625f      // 2^-8 (4x margin over 2*2^-10 tf32 bound)
#define EPSA 1.5e-4f          // covers 2*ulp(256) + mma chain rounding
#define SMEMA 131072          // A resident: 8 chunks * 128 rows * 32 tf32
#define SMEMB 16384           // one B chunk: 128 rows * 32 tf32
#define SMEM_DYN (SMEMA + 2 * SMEMB)

__device__ float    g_xx[NN];
__device__ float    g_s2[NN];          // sum |2x| per row
__device__ float    g_ee[KK];
__device__ unsigned g_emaxb;           // max |e| bits
__device__ int      g_idx[NN];
__device__ int      g_cnt[KK];
__device__ double   g_sq;
__device__ unsigned g_XT[(size_t)NN * DD];   // tf32(2x)
__device__ unsigned g_ET[(size_t)KK * DD];   // tf32(e)
__device__ int      g_cand[(size_t)NN * CAP];
__device__ int      g_ccnt[NN];

// ---- helpers ----
__device__ __forceinline__ uint32_t smem_u32(const void* p) {
    uint32_t a;
    asm("{ .reg .u64 t; cvta.to.shared.u64 t, %1; cvt.u32.u64 %0, t; }" : "=r"(a) : "l"(p));
    return a;
}
__device__ __forceinline__ void cp16(uint32_t dst, const void* src) {
    uint64_t gs;
    asm("cvta.to.global.u64 %0, %1;" : "=l"(gs) : "l"(src));
    asm volatile("cp.async.cg.shared.global [%0], [%1], 16;" :: "r"(dst), "l"(gs));
}
#define CP_COMMIT() asm volatile("cp.async.commit_group;" ::: "memory")
#define CP_WAIT1()  asm volatile("cp.async.wait_group 1;" ::: "memory")
#define CP_WAIT0()  asm volatile("cp.async.wait_group 0;" ::: "memory")
__device__ __forceinline__ void ldsm4(uint32_t a, uint32_t& r0, uint32_t& r1,
                                      uint32_t& r2, uint32_t& r3) {
    asm volatile("ldmatrix.sync.aligned.m8n8.x4.shared.b16 {%0,%1,%2,%3}, [%4];"
                 : "=r"(r0), "=r"(r1), "=r"(r2), "=r"(r3) : "r"(a));
}
__device__ __forceinline__ void mma8(float* c, const uint32_t* a, uint32_t b0, uint32_t b1) {
    asm volatile("mma.sync.aligned.m16n8k8.row.col.f32.tf32.tf32.f32 "
                 "{%0,%1,%2,%3}, {%4,%5,%6,%7}, {%8,%9}, {%0,%1,%2,%3};"
                 : "+f"(c[0]), "+f"(c[1]), "+f"(c[2]), "+f"(c[3])
                 : "r"(a[0]), "r"(a[1]), "r"(a[2]), "r"(a[3]), "r"(b0), "r"(b1));
}
__device__ __forceinline__ unsigned tf32rna(float f) {
    unsigned u;
    asm("cvt.rna.tf32.f32 %0, %1;" : "=r"(u) : "f"(f));
    return u;
}

// ---- init ----
__global__ void k_init() {
    int i = blockIdx.x * blockDim.x + threadIdx.x;
    if (i < KK) g_cnt[i] = 0;
    if (i == 0) { g_sq = 0.0; g_emaxb = 0u; }
}

// ---- prep x: exact xx (reference chain), S2, tf32(2x) ----
__global__ void k_prep_x(const float* __restrict__ x) {
    int gw = (blockIdx.x * blockDim.x + threadIdx.x) >> 5, lane = threadIdx.x & 31;
    if (gw >= NN) return;
    const float* p = x + (size_t)gw * DD;
    float s = 0.f, s2 = 0.f;
#pragma unroll
    for (int j = 0; j < 8; j++) {
        float t = p[lane + 32 * j];
        s  = __fadd_rn(s, __fmul_rn(t, t));
        s2 += fabsf(t);
        g_XT[(size_t)gw * DD + lane + 32 * j] = tf32rna(2.0f * t);
    }
#pragma unroll
    for (int off = 16; off; off >>= 1) {
        s  = __fadd_rn(s, __shfl_xor_sync(0xffffffffu, s, off));
        s2 += __shfl_xor_sync(0xffffffffu, s2, off);
    }
    if (lane == 0) { g_xx[gw] = s; g_s2[gw] = 2.0f * s2; }
}

// ---- prep e: exact ee, global max|e|, tf32(e) ----
__global__ void k_prep_e(const float* __restrict__ emb) {
    int gw = (blockIdx.x * blockDim.x + threadIdx.x) >> 5, lane = threadIdx.x & 31;
    if (gw >= KK) return;
    const float* p = emb + (size_t)gw * DD;
    float s = 0.f, m = 0.f;
#pragma unroll
    for (int j = 0; j < 8; j++) {
        float t = p[lane + 32 * j];
        s = __fadd_rn(s, __fmul_rn(t, t));
        m = fmaxf(m, fabsf(t));
        g_ET[(size_t)gw * DD + lane + 32 * j] = tf32rna(t);
    }
#pragma unroll
    for (int off = 16; off; off >>= 1) {
        s = __fadd_rn(s, __shfl_xor_sync(0xffffffffu, s, off));
        m = fmaxf(m, __shfl_xor_sync(0xffffffffu, m, off));
    }
    if (lane == 0) { g_ee[gw] = s; atomicMax(&g_emaxb, __float_as_uint(m)); }
}

// ---- B chunk load: tile t=(g>>3), k-chunk c=(g&7), 128x32 tf32, swizzled ----
__device__ __forceinline__ void bload(uint32_t sB, int g, int tid) {
    int t = g >> 3, c = g & 7;
    uint32_t base = sB + (g & 1) * SMEMB;
    const unsigned* src = &g_ET[(size_t)(t * 128) * DD + c * 32];
#pragma unroll
    for (int i = 0; i < 4; i++) {
        int unit = i * 256 + tid;
        int n = unit >> 3, u = unit & 7;
        cp16(base + n * 128 + ((u ^ (n & 7)) << 4), src + (size_t)n * DD + u * 4);
    }
}

// ---- tf32 mma GEMM + epsilon filter ----
__global__ __launch_bounds__(256, 1) void k_mma() {
    extern __shared__ __align__(128) char dsm[];
    __shared__ float    ees[128];
    __shared__ unsigned rmin[128];
    __shared__ int      scnt[128];
    __shared__ float    epsv[128];

    const int tid = threadIdx.x, lane = tid & 31, wid = tid >> 5;
    const int wm = wid & 3, wn = wid >> 2;
    const int row0 = blockIdx.x * 128;
    const uint32_t sA = smem_u32(dsm);
    const uint32_t sB = sA + SMEMA;
    const float emax = __uint_as_float(g_emaxb);

    if (tid < 128) {
        rmin[tid] = 0x7F7FFFFFu;
        scnt[tid] = 0;
        epsv[tid] = EPSC * g_s2[row0 + tid] * emax + EPSA;
    }

    // A resident: 8192 16B units
#pragma unroll
    for (int i = 0; i < 32; i++) {
        int unit = tid + i * 256;
        int c = unit >> 10, r = (unit >> 3) & 127, u = unit & 7;
        cp16(sA + c * 16384 + r * 128 + ((u ^ (r & 7)) << 4),
             &g_XT[(size_t)(row0 + r) * DD + c * 32 + u * 4]);
    }
    CP_COMMIT();
    bload(sB, 0, tid);
    CP_COMMIT();

    // ldmatrix lane constants
    const int lrow = lane & 7, q = lane >> 3;
    const int rA0 = wm * 32 + ((q & 1) << 3) + lrow;   // A frag i=0 row; i=1: +16
    const int uqA = q >> 1;
    const int nB0 = wn * 64 + ((q >> 1) << 3) + lrow;  // B pair base; +jp*16
    const int uqB = q & 1;
    const int rbase = wm * 32 + (lane >> 2);
    const int colb  = wn * 64 + ((lane & 3) << 1);
    float xr[4];
#pragma unroll
    for (int s = 0; s < 4; s++) xr[s] = g_xx[row0 + rbase + s * 8];

    float acc[2][8][4];
#pragma unroll
    for (int i = 0; i < 2; i++)
#pragma unroll
        for (int j = 0; j < 8; j++)
#pragma unroll
            for (int p = 0; p < 4; p++) acc[i][j][p] = 0.f;

    for (int g = 0; g < 256; g++) {
        const int t = g >> 3, c = g & 7;
        __syncthreads();                          // buf (g+1)&1 free (read at g-1)
        if (g + 1 < 256) { bload(sB, g + 1, tid); CP_COMMIT(); CP_WAIT1(); }
        else             { CP_WAIT0(); }
        __syncthreads();                          // chunk g visible to all
        if (c == 0 && tid < 128) ees[tid] = g_ee[t * 128 + tid];

        const uint32_t aCh = sA + c * 16384;
        const uint32_t bCh = sB + (g & 1) * SMEMB;
#pragma unroll
        for (int s = 0; s < 4; s++) {
            uint32_t a0[4], a1[4];
            {
                int u = s * 2 + uqA;
                ldsm4(aCh + rA0 * 128 + ((u ^ (rA0 & 7)) << 4), a0[0], a0[1], a0[2], a0[3]);
                int r1 = rA0 + 16;
                ldsm4(aCh + r1 * 128 + ((u ^ (r1 & 7)) << 4), a1[0], a1[1], a1[2], a1[3]);
            }
#pragma unroll
            for (int jp = 0; jp < 4; jp++) {
                uint32_t b0, b1, b2, b3;
                int n = nB0 + jp * 16;
                int u = s * 2 + uqB;
                ldsm4(bCh + n * 128 + ((u ^ (n & 7)) << 4), b0, b1, b2, b3);
                mma8(acc[0][jp * 2],     a0, b0, b1);
                mma8(acc[0][jp * 2 + 1], a0, b2, b3);
                mma8(acc[1][jp * 2],     a1, b0, b1);
                mma8(acc[1][jp * 2 + 1], a1, b2, b3);
            }
        }

        if (c == 7) {                             // tile t epilogue (uniform branch)
            float d[2][8][4];
            float lm[4] = {3.4e38f, 3.4e38f, 3.4e38f, 3.4e38f};
#pragma unroll
            for (int i = 0; i < 2; i++)
#pragma unroll
                for (int j = 0; j < 8; j++)
#pragma unroll
                    for (int p = 0; p < 4; p++) {
                        int slot = i * 2 + (p >> 1);
                        float ec = ees[colb + j * 8 + (p & 1)];
                        float dd = (xr[slot] + ec) - acc[i][j][p];
                        d[i][j][p] = dd;
                        lm[slot] = fminf(lm[slot], dd);
                        acc[i][j][p] = 0.f;
                    }
#pragma unroll
            for (int s = 0; s < 4; s++)
                atomicMin(&rmin[rbase + s * 8], __float_as_uint(lm[s]));
            __syncthreads();
            float thr[4];
#pragma unroll
            for (int s = 0; s < 4; s++)
                thr[s] = __uint_as_float(rmin[rbase + s * 8]) + epsv[rbase + s * 8];
#pragma unroll
            for (int i = 0; i < 2; i++)
#pragma unroll
                for (int j = 0; j < 8; j++)
#pragma unroll
                    for (int p = 0; p < 4; p++) {
                        int slot = i * 2 + (p >> 1);
                        if (d[i][j][p] < thr[slot]) {
                            int rl = rbase + slot * 8;
                            int pos = atomicAdd(&scnt[rl], 1);
                            if (pos < CAP)
                                g_cand[(size_t)(row0 + rl) * CAP + pos] =
                                    t * 128 + colb + j * 8 + (p & 1);
                        }
                    }
        }
    }
    __syncthreads();
    if (tid < 128) g_ccnt[row0 + tid] = scnt[tid];
}

// ---- exact rescore: bit-exact reference chain over candidates ----
__global__ void k_rescore(const float* __restrict__ x, const float* __restrict__ emb) {
    int gw = (blockIdx.x * blockDim.x + threadIdx.x) >> 5, lane = threadIdx.x & 31;
    if (gw >= NN) return;
    int cnt = g_ccnt[gw];
    float xr = g_xx[gw];
    const float* xp = x + (size_t)gw * DD;
    unsigned long long best = ~0ull;
    if (cnt <= CAP) {
        for (int ci = lane; ci < cnt; ci += 32) {
            int k = g_cand[(size_t)gw * CAP + ci];
            const float* ep = emb + (size_t)k * DD;
            float acc = 0.f;
            for (int i = 0; i < DD; i++)
                acc = __fmaf_rn(2.0f * xp[i], ep[i], acc);
            float dd = __fadd_rn(__fadd_rn(xr, g_ee[k]), -acc);
            unsigned long long pk =
                (((unsigned long long)__float_as_uint(dd)) << 32) | (unsigned)k;
            if (pk < best) best = pk;
        }
    } else {                                       // overflow: exact full scan
        for (int k = lane; k < KK; k += 32) {
            const float* ep = emb + (size_t)k * DD;
            float acc = 0.f;
            for (int i = 0; i < DD; i++)
                acc = __fmaf_rn(2.0f * xp[i], ep[i], acc);
            float dd = __fadd_rn(__fadd_rn(xr, g_ee[k]), -acc);
            unsigned long long pk =
                (((unsigned long long)__float_as_uint(dd)) << 32) | (unsigned)k;
            if (pk < best) best = pk;
        }
    }
#pragma unroll
    for (int off = 16; off; off >>= 1) {
        unsigned long long o = __shfl_xor_sync(0xffffffffu, best, off);
        if (o < best) best = o;
    }
    if (lane == 0) g_idx[gw] = (int)(best & 0xffffffffull);
}

// ---- gather + ST output + MSE ----
__global__ void k_gather(const float* __restrict__ x, const float* __restrict__ emb,
                         const float* __restrict__ mask, float* __restrict__ out) {
    __shared__ double sh[8];
    double local = 0.0;
    for (int id = blockIdx.x * blockDim.x + threadIdx.x; id < NN * DD;
         id += gridDim.x * blockDim.x) {
        int row = id >> 8, col = id & 255;
        float qv = __fmul_rn(emb[(size_t)g_idx[row] * DD + col], mask[row]);
        float xv = x[id];
        float d1 = __fadd_rn(qv, -xv);
        out[id]  = __fadd_rn(xv, d1);
        local += (double)__fmul_rn(d1, d1);
    }
#pragma unroll
    for (int off = 16; off; off >>= 1) local += __shfl_xor_sync(0xffffffffu, local, off);
    int lane = threadIdx.x & 31, w = threadIdx.x >> 5;
    if (lane == 0) sh[w] = local;
    __syncthreads();
    if (threadIdx.x == 0) {
        double s = 0.0;
        for (int i = 0; i < (int)(blockDim.x >> 5); i++) s += sh[i];
        atomicAdd(&g_sq, s);
    }
}
__global__ void k_hist(float* __restrict__ out) {
    int i = blockIdx.x * blockDim.x + threadIdx.x;
    if (i < NN) {
        int c = g_idx[i];
        atomicAdd(&g_cnt[c], 1);
        out[OUT_IDX_BASE + i] = (float)c;
    }
}
__global__ void k_final(float* __restrict__ out) {
    __shared__ double sh[8];
    double local = 0.0;
    for (int k = threadIdx.x; k < KK; k += blockDim.x) {
        float p = __fmul_rn((float)g_cnt[k], 1.0f / 32768.0f);
        local += (double)__fmul_rn(p, logf(__fadd_rn(p, 1e-8f)));
    }
#pragma unroll
    for (int off = 16; off; off >>= 1) local += __shfl_xor_sync(0xffffffffu, local, off);
    int lane = threadIdx.x & 31, w = threadIdx.x >> 5;
    if (lane == 0) sh[w] = local;
    __syncthreads();
    if (threadIdx.x == 0) {
        double H = 0.0;
        for (int i = 0; i < (int)(blockDim.x >> 5); i++) H += sh[i];
        double mse = g_sq / (double)(NN * DD);
        float ql = (float)mse;
        out[OUT_SCALAR_BASE + 0] = __fmul_rn(0.25f, ql);
        out[OUT_SCALAR_BASE + 1] = ql;
        out[OUT_SCALAR_BASE + 2] = expf(-(float)H);
    }
}

extern "C" void kernel_launch(void* const* d_in, const int* in_sizes, int n_in,
                              void* d_out, int out_size) {
    const float* x    = (const float*)d_in[0];
    const float* emb  = (const float*)d_in[1];
    const float* mask = (const float*)d_in[2];
    float* out = (float*)d_out;

    cudaFuncSetAttribute(k_mma, cudaFuncAttributeMaxDynamicSharedMemorySize, SMEM_DYN);

    k_init<<<16, 256>>>();
    k_prep_x<<<(NN * 32) / 256, 256>>>(x);
    k_prep_e<<<(KK * 32) / 256, 256>>>(emb);
    k_mma<<<NN / 128, 256, SMEM_DYN>>>();
    k_rescore<<<(NN * 32) / 256, 256>>>(x, emb);
    k_gather<<<1024, 256>>>(x, emb, mask, out);
    k_hist<<<(NN + 255) / 256, 256>>>(out);
    k_final<<<1, 256>>>(out);
}

// round 7
// speedup vs baseline: 2.4811x; 1.0981x over previous
#include <cuda_runtime.h>
#include <math.h>
#include <stdint.h>

#define NN 32768
#define DD 256
#define KK 4096
#define OUT_SCALAR_BASE (NN * DD)
#define OUT_IDX_BASE    (NN * DD + 3)
#define CAP 24
#define EPSC 0.00390625f      // 2^-8 (4x margin over 2*2^-10 tf32 bound)
#define EPSA 1.5e-4f          // covers 2*ulp(256) + mma chain rounding
#define SMEMA 131072          // A resident: 8 sub-chunks * 128 rows * 32 tf32
#define SMEMB 32768           // one B 64-dim chunk (2 sub-chunks)
#define SMEM_DYN (SMEMA + 2 * SMEMB)

__device__ float    g_xx[NN];
__device__ float    g_s2[NN];
__device__ float    g_ee[KK];
__device__ unsigned g_emaxb;
__device__ int      g_idx[NN];
__device__ int      g_cnt[KK];
__device__ double   g_sq;
__device__ unsigned g_XT[(size_t)NN * DD];   // tf32(2x)
__device__ unsigned g_ET[(size_t)KK * DD];   // tf32(e)
__device__ int      g_cand[(size_t)NN * CAP];
__device__ int      g_ccnt[NN];

// ---- helpers ----
__device__ __forceinline__ uint32_t smem_u32(const void* p) {
    uint32_t a;
    asm("{ .reg .u64 t; cvta.to.shared.u64 t, %1; cvt.u32.u64 %0, t; }" : "=r"(a) : "l"(p));
    return a;
}
__device__ __forceinline__ void cp16(uint32_t dst, const void* src) {
    uint64_t gs;
    asm("cvta.to.global.u64 %0, %1;" : "=l"(gs) : "l"(src));
    asm volatile("cp.async.cg.shared.global [%0], [%1], 16;" :: "r"(dst), "l"(gs));
}
#define CP_COMMIT() asm volatile("cp.async.commit_group;" ::: "memory")
#define CP_WAIT0()  asm volatile("cp.async.wait_group 0;" ::: "memory")
__device__ __forceinline__ void ldsm4(uint32_t a, uint32_t& r0, uint32_t& r1,
                                      uint32_t& r2, uint32_t& r3) {
    asm volatile("ldmatrix.sync.aligned.m8n8.x4.shared.b16 {%0,%1,%2,%3}, [%4];"
                 : "=r"(r0), "=r"(r1), "=r"(r2), "=r"(r3) : "r"(a));
}
__device__ __forceinline__ void mma8(float* c, const uint32_t* a, uint32_t b0, uint32_t b1) {
    asm volatile("mma.sync.aligned.m16n8k8.row.col.f32.tf32.tf32.f32 "
                 "{%0,%1,%2,%3}, {%4,%5,%6,%7}, {%8,%9}, {%0,%1,%2,%3};"
                 : "+f"(c[0]), "+f"(c[1]), "+f"(c[2]), "+f"(c[3])
                 : "r"(a[0]), "r"(a[1]), "r"(a[2]), "r"(a[3]), "r"(b0), "r"(b1));
}
__device__ __forceinline__ unsigned tf32rna(float f) {
    unsigned u;
    asm("cvt.rna.tf32.f32 %0, %1;" : "=r"(u) : "f"(f));
    return u;
}

// ---- init ----
__global__ void k_init() {
    int i = blockIdx.x * blockDim.x + threadIdx.x;
    if (i < KK) g_cnt[i] = 0;
    if (i == 0) { g_sq = 0.0; g_emaxb = 0u; }
}

// ---- prep x: exact xx (reference chain), S2, tf32(2x) ----
__global__ void k_prep_x(const float* __restrict__ x) {
    int gw = (blockIdx.x * blockDim.x + threadIdx.x) >> 5, lane = threadIdx.x & 31;
    if (gw >= NN) return;
    const float* p = x + (size_t)gw * DD;
    float s = 0.f, s2 = 0.f;
#pragma unroll
    for (int j = 0; j < 8; j++) {
        float t = p[lane + 32 * j];
        s  = __fadd_rn(s, __fmul_rn(t, t));
        s2 += fabsf(t);
        g_XT[(size_t)gw * DD + lane + 32 * j] = tf32rna(2.0f * t);
    }
#pragma unroll
    for (int off = 16; off; off >>= 1) {
        s  = __fadd_rn(s, __shfl_xor_sync(0xffffffffu, s, off));
        s2 += __shfl_xor_sync(0xffffffffu, s2, off);
    }
    if (lane == 0) { g_xx[gw] = s; g_s2[gw] = 2.0f * s2; }
}

// ---- prep e: exact ee, global max|e|, tf32(e) ----
__global__ void k_prep_e(const float* __restrict__ emb) {
    int gw = (blockIdx.x * blockDim.x + threadIdx.x) >> 5, lane = threadIdx.x & 31;
    if (gw >= KK) return;
    const float* p = emb + (size_t)gw * DD;
    float s = 0.f, m = 0.f;
#pragma unroll
    for (int j = 0; j < 8; j++) {
        float t = p[lane + 32 * j];
        s = __fadd_rn(s, __fmul_rn(t, t));
        m = fmaxf(m, fabsf(t));
        g_ET[(size_t)gw * DD + lane + 32 * j] = tf32rna(t);
    }
#pragma unroll
    for (int off = 16; off; off >>= 1) {
        s = __fadd_rn(s, __shfl_xor_sync(0xffffffffu, s, off));
        m = fmaxf(m, __shfl_xor_sync(0xffffffffu, m, off));
    }
    if (lane == 0) { g_ee[gw] = s; atomicMax(&g_emaxb, __float_as_uint(m)); }
}

// ---- B 64-dim chunk load: tile t=(g>>2), c=(g&3); 2 sub-chunks of 128x32 ----
__device__ __forceinline__ void bload(uint32_t sB, int g, int tid) {
    const int t = g >> 2, c = g & 3;
    const uint32_t base = sB + (g & 1) * SMEMB;
    const unsigned* src = &g_ET[(size_t)(t * 128) * DD + c * 64];
#pragma unroll
    for (int i = 0; i < 8; i++) {
        int unit = i * 256 + tid;
        int h = unit >> 10, n = (unit >> 3) & 127, u = unit & 7;
        cp16(base + h * 16384 + n * 128 + ((u ^ (n & 7)) << 4),
             src + (size_t)n * DD + h * 32 + u * 4);
    }
}

// ---- tf32 mma GEMM + epsilon filter ----
__global__ __launch_bounds__(256, 1) void k_mma() {
    extern __shared__ __align__(128) char dsm[];
    __shared__ float    ees[128];
    __shared__ unsigned rmin[128];
    __shared__ int      scnt[128];
    __shared__ float    epsv[128];

    const int tid = threadIdx.x, lane = tid & 31, wid = tid >> 5;
    const int wm = wid & 3, wn = wid >> 2;
    const int row0 = blockIdx.x * 128;
    const uint32_t sA = smem_u32(dsm);
    const uint32_t sB = sA + SMEMA;
    const float emax = __uint_as_float(g_emaxb);

    if (tid < 128) {
        rmin[tid] = 0x7F7FFFFFu;
        scnt[tid] = 0;
        epsv[tid] = EPSC * g_s2[row0 + tid] * emax + EPSA;
    }

    // A resident: 8192 16B units, 8 sub-chunks of (128 rows x 32 dims)
#pragma unroll
    for (int i = 0; i < 32; i++) {
        int unit = tid + i * 256;
        int sc = unit >> 10, r = (unit >> 3) & 127, u = unit & 7;
        cp16(sA + sc * 16384 + r * 128 + ((u ^ (r & 7)) << 4),
             &g_XT[(size_t)(row0 + r) * DD + sc * 32 + u * 4]);
    }
    bload(sB, 0, tid);
    CP_COMMIT();

    // ldmatrix lane constants
    const int lrow = lane & 7, q = lane >> 3;
    const int rA0 = wm * 32 + ((q & 1) << 3) + lrow;
    const int uqA = q >> 1;
    const int nB0 = wn * 64 + ((q >> 1) << 3) + lrow;
    const int uqB = q & 1;
    const int rbase = wm * 32 + (lane >> 2);
    const int colb  = wn * 64 + ((lane & 3) << 1);
    float xr[4];
#pragma unroll
    for (int s = 0; s < 4; s++) xr[s] = g_xx[row0 + rbase + s * 8];

    float acc[2][8][4];
#pragma unroll
    for (int i = 0; i < 2; i++)
#pragma unroll
        for (int j = 0; j < 8; j++)
#pragma unroll
            for (int p = 0; p < 4; p++) acc[i][j][p] = 0.f;

#pragma unroll 1
    for (int t = 0; t < 32; t++) {
#pragma unroll
        for (int c = 0; c < 4; c++) {
            const int g = t * 4 + c;
            // 1 barrier per chunk: publishes chunk g AND retires buffer g-1
            CP_WAIT0();
            __syncthreads();
            if (g + 1 < 128) { bload(sB, g + 1, tid); CP_COMMIT(); }
            if (c == 0 && tid < 128) ees[tid] = g_ee[t * 128 + tid];

            const uint32_t bCh = sB + (g & 1) * SMEMB;
#pragma unroll
            for (int s = 0; s < 8; s++) {
                const uint32_t aCh = sA + (c * 2 + (s >> 2)) * 16384;
                const uint32_t bSc = bCh + (s >> 2) * 16384;
                const int us = (s & 3) * 2;
                uint32_t a0[4], a1[4];
                {
                    int u = us + uqA;
                    ldsm4(aCh + rA0 * 128 + ((u ^ (rA0 & 7)) << 4),
                          a0[0], a0[1], a0[2], a0[3]);
                    int r1 = rA0 + 16;
                    ldsm4(aCh + r1 * 128 + ((u ^ (r1 & 7)) << 4),
                          a1[0], a1[1], a1[2], a1[3]);
                }
#pragma unroll
                for (int jp = 0; jp < 4; jp++) {
                    uint32_t b0, b1, b2, b3;
                    int n = nB0 + jp * 16;
                    int u = us + uqB;
                    ldsm4(bSc + n * 128 + ((u ^ (n & 7)) << 4), b0, b1, b2, b3);
                    mma8(acc[0][jp * 2],     a0, b0, b1);
                    mma8(acc[0][jp * 2 + 1], a0, b2, b3);
                    mma8(acc[1][jp * 2],     a1, b0, b1);
                    mma8(acc[1][jp * 2 + 1], a1, b2, b3);
                }
            }
        }

        // ---- tile epilogue: local mins -> shared rmin -> threshold/append ----
        {
            float lm[4] = {3.4e38f, 3.4e38f, 3.4e38f, 3.4e38f};
#pragma unroll
            for (int i = 0; i < 2; i++)
#pragma unroll
                for (int j = 0; j < 8; j++)
#pragma unroll
                    for (int p = 0; p < 4; p++) {
                        int slot = i * 2 + (p >> 1);
                        float dd = (xr[slot] + ees[colb + j * 8 + (p & 1)]) - acc[i][j][p];
                        lm[slot] = fminf(lm[slot], dd);
                    }
#pragma unroll
            for (int s = 0; s < 4; s++)
                atomicMin(&rmin[rbase + s * 8], __float_as_uint(lm[s]));
            __syncthreads();
            float thr[4];
#pragma unroll
            for (int s = 0; s < 4; s++)
                thr[s] = __uint_as_float(rmin[rbase + s * 8]) + epsv[rbase + s * 8];
#pragma unroll
            for (int i = 0; i < 2; i++)
#pragma unroll
                for (int j = 0; j < 8; j++)
#pragma unroll
                    for (int p = 0; p < 4; p++) {
                        int slot = i * 2 + (p >> 1);
                        float dd = (xr[slot] + ees[colb + j * 8 + (p & 1)]) - acc[i][j][p];
                        if (dd < thr[slot]) {
                            int rl = rbase + slot * 8;
                            int pos = atomicAdd(&scnt[rl], 1);
                            if (pos < CAP)
                                g_cand[(size_t)(row0 + rl) * CAP + pos] =
                                    t * 128 + colb + j * 8 + (p & 1);
                        }
                        acc[i][j][p] = 0.f;
                    }
        }
    }
    __syncthreads();
    if (tid < 128) g_ccnt[row0 + tid] = scnt[tid];
}

// ---- exact rescore (bit-exact reference chain) + fused histogram/idx out ----
__global__ void k_rescore(const float* __restrict__ x, const float* __restrict__ emb,
                          float* __restrict__ out) {
    int gw = (blockIdx.x * blockDim.x + threadIdx.x) >> 5, lane = threadIdx.x & 31;
    if (gw >= NN) return;
    int cnt = g_ccnt[gw];
    float xr = g_xx[gw];
    const float* xp = x + (size_t)gw * DD;
    unsigned long long best = ~0ull;
    if (cnt <= CAP) {
        for (int ci = lane; ci < cnt; ci += 32) {
            int k = g_cand[(size_t)gw * CAP + ci];
            const float* ep = emb + (size_t)k * DD;
            float acc = 0.f;
            for (int i = 0; i < DD; i++)
                acc = __fmaf_rn(2.0f * xp[i], ep[i], acc);
            float dd = __fadd_rn(__fadd_rn(xr, g_ee[k]), -acc);
            unsigned long long pk =
                (((unsigned long long)__float_as_uint(dd)) << 32) | (unsigned)k;
            if (pk < best) best = pk;
        }
    } else {                                       // overflow: exact full scan
        for (int k = lane; k < KK; k += 32) {
            const float* ep = emb + (size_t)k * DD;
            float acc = 0.f;
            for (int i = 0; i < DD; i++)
                acc = __fmaf_rn(2.0f * xp[i], ep[i], acc);
            float dd = __fadd_rn(__fadd_rn(xr, g_ee[k]), -acc);
            unsigned long long pk =
                (((unsigned long long)__float_as_uint(dd)) << 32) | (unsigned)k;
            if (pk < best) best = pk;
        }
    }
#pragma unroll
    for (int off = 16; off; off >>= 1) {
        unsigned long long o = __shfl_xor_sync(0xffffffffu, best, off);
        if (o < best) best = o;
    }
    if (lane == 0) {
        int c = (int)(best & 0xffffffffull);
        g_idx[gw] = c;
        atomicAdd(&g_cnt[c], 1);
        out[OUT_IDX_BASE + gw] = (float)c;
    }
}

// ---- gather + ST output + MSE (float4, identical per-element rounding) ----
__global__ void k_gather(const float* __restrict__ x, const float* __restrict__ emb,
                         const float* __restrict__ mask, float* __restrict__ out) {
    __shared__ double sh[8];
    double local = 0.0;
    const int n4 = NN * DD / 4;
    for (int id4 = blockIdx.x * blockDim.x + threadIdx.x; id4 < n4;
         id4 += gridDim.x * blockDim.x) {
        int row = id4 >> 6;
        float m = mask[row];
        float4 e4 = *(const float4*)&emb[(size_t)g_idx[row] * DD + (id4 & 63) * 4];
        float4 x4 = *(const float4*)&x[(size_t)id4 * 4];
        float4 o4;
        float q, d1;
        q = __fmul_rn(e4.x, m); d1 = __fadd_rn(q, -x4.x); o4.x = __fadd_rn(x4.x, d1);
        local += (double)__fmul_rn(d1, d1);
        q = __fmul_rn(e4.y, m); d1 = __fadd_rn(q, -x4.y); o4.y = __fadd_rn(x4.y, d1);
        local += (double)__fmul_rn(d1, d1);
        q = __fmul_rn(e4.z, m); d1 = __fadd_rn(q, -x4.z); o4.z = __fadd_rn(x4.z, d1);
        local += (double)__fmul_rn(d1, d1);
        q = __fmul_rn(e4.w, m); d1 = __fadd_rn(q, -x4.w); o4.w = __fadd_rn(x4.w, d1);
        local += (double)__fmul_rn(d1, d1);
        *(float4*)&out[(size_t)id4 * 4] = o4;
    }
#pragma unroll
    for (int off = 16; off; off >>= 1) local += __shfl_xor_sync(0xffffffffu, local, off);
    int lane = threadIdx.x & 31, w = threadIdx.x >> 5;
    if (lane == 0) sh[w] = local;
    __syncthreads();
    if (threadIdx.x == 0) {
        double s = 0.0;
        for (int i = 0; i < (int)(blockDim.x >> 5); i++) s += sh[i];
        atomicAdd(&g_sq, s);
    }
}
__global__ void k_final(float* __restrict__ out) {
    __shared__ double sh[8];
    double local = 0.0;
    for (int k = threadIdx.x; k < KK; k += blockDim.x) {
        float p = __fmul_rn((float)g_cnt[k], 1.0f / 32768.0f);
        local += (double)__fmul_rn(p, logf(__fadd_rn(p, 1e-8f)));
    }
#pragma unroll
    for (int off = 16; off; off >>= 1) local += __shfl_xor_sync(0xffffffffu, local, off);
    int lane = threadIdx.x & 31, w = threadIdx.x >> 5;
    if (lane == 0) sh[w] = local;
    __syncthreads();
    if (threadIdx.x == 0) {
        double H = 0.0;
        for (int i = 0; i < (int)(blockDim.x >> 5); i++) H += sh[i];
        double mse = g_sq / (double)(NN * DD);
        float ql = (float)mse;
        out[OUT_SCALAR_BASE + 0] = __fmul_rn(0.25f, ql);
        out[OUT_SCALAR_BASE + 1] = ql;
        out[OUT_SCALAR_BASE + 2] = expf(-(float)H);
    }
}

extern "C" void kernel_launch(void* const* d_in, const int* in_sizes, int n_in,
                              void* d_out, int out_size) {
    const float* x    = (const float*)d_in[0];
    const float* emb  = (const float*)d_in[1];
    const float* mask = (const float*)d_in[2];
    float* out = (float*)d_out;

    cudaFuncSetAttribute(k_mma, cudaFuncAttributeMaxDynamicSharedMemorySize, SMEM_DYN);

    k_init<<<16, 256>>>();
    k_prep_x<<<(NN * 32) / 256, 256>>>(x);
    k_prep_e<<<(KK * 32) / 256, 256>>>(emb);
    k_mma<<<NN / 128, 256, SMEM_DYN>>>();
    k_rescore<<<(NN * 32) / 256, 256>>>(x, emb, out);
    k_gather<<<1024, 256>>>(x, emb, mask, out);
    k_final<<<1, 256>>>(out);
}